// round 4
// baseline (speedup 1.0000x reference)
#include <cuda_runtime.h>

#define N_FEAT_COLS 9
#define CARD 50000
#define EMB 128
#define EDGE_DIM 27

#define EPB 64                 // edges per block
#define REFS (3 * EPB)         // 192 node refs per block
#define BLOCK 256
#define WARPS (BLOCK / 32)
#define RPW (REFS / WARPS)     // 24 refs per warp
#define EPW (EPB / WARPS)      // 8 edges per warp

// smem: acc[REFS][EMB] floats + xrow[REFS][10] ints + nid[REFS] ints
#define SMEM_BYTES (REFS * EMB * 4 + REFS * 10 * 4 + REFS * 4)

__device__ float g_v[EDGE_DIM];
__device__ float g_c;

__global__ void precompute_v_kernel(const float* __restrict__ edge_w,
                                    const float* __restrict__ edge_b,
                                    const float* __restrict__ out_w,
                                    const float* __restrict__ out_b) {
    int j = threadIdx.x;
    if (j < EDGE_DIM) {
        float s = 0.f;
        #pragma unroll 8
        for (int k = 0; k < EMB; k++) s += out_w[k] * edge_w[k * EDGE_DIM + j];
        g_v[j] = s;
    }
    if (j == EDGE_DIM) {
        float s = out_b[0];
        #pragma unroll 8
        for (int k = 0; k < EMB; k++) s += out_w[k] * edge_b[k];
        g_c = s;
    }
}

__device__ __forceinline__ float4 ld4_hot(const float* __restrict__ p) {
    float4 v;
    asm("{\n\t"
        ".reg .b64 pol;\n\t"
        "createpolicy.fractional.L2::evict_last.b64 pol, 1.0;\n\t"
        "ld.global.nc.L2::cache_hint.v4.f32 {%0,%1,%2,%3}, [%4], pol;\n\t"
        "}"
        : "=f"(v.x), "=f"(v.y), "=f"(v.z), "=f"(v.w) : "l"(p));
    return v;
}
__device__ __forceinline__ float4 ld4(const float* __restrict__ p) {
    return *reinterpret_cast<const float4*>(p);
}

__global__ __launch_bounds__(BLOCK)
void edge_pred_phased(const int* __restrict__ x,
                      const int* __restrict__ src,
                      const int* __restrict__ dst,
                      const int* __restrict__ neg_dst,
                      const float* __restrict__ msg,
                      const float* __restrict__ emb_type,
                      const float* __restrict__ emb_feats,
                      const float* __restrict__ out_w,
                      float* __restrict__ out,
                      int E) {
    extern __shared__ float smem[];
    float* acc  = smem;                              // REFS*EMB floats
    int*   xrow = (int*)(smem + REFS * EMB);         // REFS*10 ints
    int*   nid  = xrow + REFS * 10;                  // REFS ints

    const unsigned FULL = 0xffffffffu;
    int tid  = threadIdx.x;
    int lane = tid & 31;
    int w    = tid >> 5;
    int lane4 = lane * 4;

    long long ebase = (long long)blockIdx.x * EPB;
    int nE = E - (int)ebase;
    if (nE > EPB) nE = EPB;

    // ---- 1) node ids (refs: [0,EPB)=src, [EPB,2EPB)=dst, [2EPB,3EPB)=neg)
    for (int r = tid; r < REFS; r += BLOCK) {
        int l = r & (EPB - 1);
        int g = r >> 6;   // EPB == 64
        int n = 0;
        if (l < nE) {
            const int* arr = (g == 0) ? src : (g == 1) ? dst : neg_dst;
            n = __ldcs(arr + ebase + l);
        }
        nid[r] = n;
    }
    __syncthreads();

    // ---- 2) x rows (streaming)
    for (int i = tid; i < REFS * 10; i += BLOCK) {
        int r = i / 10, c = i - r * 10;
        xrow[i] = __ldcs(x + (long long)nid[r] * 10 + c);
    }
    __syncthreads();

    // ---- 3) init accumulators with emb_type[t]
    for (int i = tid; i < REFS * EMB; i += BLOCK) {
        int r = i >> 7, c = i & 127;
        acc[i] = __ldg(emb_type + xrow[r * 10] * EMB + c);
    }
    __syncthreads();

    // ---- 4) column-phased gathers: all blocks sweep h = 0..8 in order,
    //         so the chip-wide instantaneous working set is one 25.6MB table.
    int wbase = w * RPW;
    #pragma unroll 1
    for (int h = 0; h < N_FEAT_COLS; h++) {
        int tcol = (h < 4) ? 0 : (h == 4) ? 1 : 2;
        const float* table = emb_feats + (long long)h * CARD * EMB;
        #pragma unroll 8
        for (int k = 0; k < RPW; k++) {
            int r = wbase + k;
            if (xrow[r * 10] == tcol) {
                int f = xrow[r * 10 + h + 1];
                float4 e = ld4_hot(table + (long long)f * EMB + lane4);
                float4* ap = (float4*)(acc + r * EMB + lane4);
                float4 a = *ap;
                a.x += e.x; a.y += e.y; a.z += e.z; a.w += e.w;
                *ap = a;
            }
        }
        __syncthreads();
    }

    // ---- 5) finalize: each warp handles EPW edges
    float4 ow = ld4(out_w + lane4);
    float  c0 = g_c;
    #pragma unroll
    for (int j = 0; j < EPW; j++) {
        int l = w * EPW + j;
        if (l >= nE) break;
        long long ge = ebase + l;
        float4 hs = *(float4*)(acc + l * EMB + lane4);
        float4 hd = *(float4*)(acc + (EPB + l) * EMB + lane4);
        float4 hn = *(float4*)(acc + (2 * EPB + l) * EMB + lane4);

        float pp = fmaxf(hs.x + hd.x, 0.f) * ow.x
                 + fmaxf(hs.y + hd.y, 0.f) * ow.y
                 + fmaxf(hs.z + hd.z, 0.f) * ow.z
                 + fmaxf(hs.w + hd.w, 0.f) * ow.w;
        float np = fmaxf(hs.x + hn.x, 0.f) * ow.x
                 + fmaxf(hs.y + hn.y, 0.f) * ow.y
                 + fmaxf(hs.z + hn.z, 0.f) * ow.z
                 + fmaxf(hs.w + hn.w, 0.f) * ow.w;

        float m = 0.f;
        if (lane < EDGE_DIM)
            m = __ldcs(msg + ge * EDGE_DIM + lane) * g_v[lane];
        pp += m;
        np += m;

        #pragma unroll
        for (int o = 16; o > 0; o >>= 1) {
            pp += __shfl_xor_sync(FULL, pp, o);
            np += __shfl_xor_sync(FULL, np, o);
        }
        if (lane == 0) {
            out[ge]     = pp + c0;
            out[E + ge] = np + c0;
        }
    }
}

extern "C" void kernel_launch(void* const* d_in, const int* in_sizes, int n_in,
                              void* d_out, int out_size) {
    const int*   x        = (const int*)  d_in[0];
    const int*   src      = (const int*)  d_in[1];
    const int*   dst      = (const int*)  d_in[2];
    const int*   neg_dst  = (const int*)  d_in[3];
    const float* msg      = (const float*)d_in[4];
    const float* emb_type = (const float*)d_in[5];
    const float* emb_feats= (const float*)d_in[6];
    const float* edge_w   = (const float*)d_in[7];
    const float* edge_b   = (const float*)d_in[8];
    const float* out_w    = (const float*)d_in[9];
    const float* out_b    = (const float*)d_in[10];
    float* out = (float*)d_out;

    int E = in_sizes[1];

    static bool attr_set = false;
    if (!attr_set) {
        cudaFuncSetAttribute(edge_pred_phased,
                             cudaFuncAttributeMaxDynamicSharedMemorySize,
                             SMEM_BYTES);
        attr_set = true;
    }

    precompute_v_kernel<<<1, 32>>>(edge_w, edge_b, out_w, out_b);

    int blocks = (E + EPB - 1) / EPB;
    edge_pred_phased<<<blocks, BLOCK, SMEM_BYTES>>>(x, src, dst, neg_dst, msg,
                                                    emb_type, emb_feats, out_w,
                                                    out, E);
}

// round 5
// speedup vs baseline: 3.9150x; 3.9150x over previous
#include <cuda_runtime.h>

#define N_FEAT_COLS 9
#define CARD 50000
#define EMB 128
#define EDGE_DIM 27

__device__ float g_v[EDGE_DIM];
__device__ float g_c;

__global__ void precompute_v_kernel(const float* __restrict__ edge_w,
                                    const float* __restrict__ edge_b,
                                    const float* __restrict__ out_w,
                                    const float* __restrict__ out_b) {
    int j = threadIdx.x;
    if (j < EDGE_DIM) {
        float s = 0.f;
        #pragma unroll 8
        for (int k = 0; k < EMB; k++) s += out_w[k] * edge_w[k * EDGE_DIM + j];
        g_v[j] = s;
    }
    if (j == EDGE_DIM) {
        float s = out_b[0];
        #pragma unroll 8
        for (int k = 0; k < EMB; k++) s += out_w[k] * edge_b[k];
        g_c = s;
    }
}

__device__ __forceinline__ float4 ld4g(const float* __restrict__ p) {
    return __ldg(reinterpret_cast<const float4*>(p));
}
__device__ __forceinline__ float4 ld4(const float* __restrict__ p) {
    return *reinterpret_cast<const float4*>(p);
}

__global__ __launch_bounds__(256)
void edge_pred_kernel(const int* __restrict__ x,
                      const int* __restrict__ src,
                      const int* __restrict__ dst,
                      const int* __restrict__ neg_dst,
                      const float* __restrict__ msg,
                      const float* __restrict__ emb_type,
                      const float* __restrict__ emb_feats,
                      const float* __restrict__ out_w,
                      float* __restrict__ out,
                      int E) {
    const unsigned FULL = 0xffffffffu;
    int warp = (blockIdx.x * blockDim.x + threadIdx.x) >> 5;
    int lane = threadIdx.x & 31;
    if (warp >= E) return;
    int e = warp;
    int lane4 = lane * 4;

    int s  = __ldcs(src + e);
    int d  = __ldcs(dst + e);
    int nd = __ldcs(neg_dst + e);

    // Lanes 0..29 cooperatively load the three 10-int x rows.
    int which = lane / 10;          // 0:src 1:dst 2:neg
    int off   = lane - which * 10;
    int nid   = (which == 0) ? s : (which == 1) ? d : nd;
    int rv = 0;
    if (lane < 30) rv = __ldcs(x + (long long)nid * 10 + off);

    // msg dot (independent, issue early)
    float m = 0.f;
    if (lane < EDGE_DIM)
        m = __ldcs(msg + (long long)e * EDGE_DIM + lane) * g_v[lane];

    // ---- compute all types / feature indices up front (shuffles only) ----
    int t0 = __shfl_sync(FULL, rv, 0);
    int t1 = __shfl_sync(FULL, rv, 10);
    int t2 = __shfl_sync(FULL, rv, 20);
    // TYPE_PER_COL = (0,0,0,0,1,2,2,2,2): t==0 -> h 0..3, t==1 -> h 4, t==2 -> h 5..8
    int h00 = (t0 == 0) ? 0 : (t0 == 1) ? 4 : 5;
    int h01 = (t1 == 0) ? 0 : (t1 == 1) ? 4 : 5;
    int h02 = (t2 == 0) ? 0 : (t2 == 1) ? 4 : 5;
    int nh0 = (t0 == 1) ? 1 : 4;
    int nh1 = (t1 == 1) ? 1 : 4;
    int nh2 = (t2 == 1) ? 1 : 4;

    int f0[4], f1[4], f2[4];
    #pragma unroll
    for (int i = 0; i < 4; i++) {
        f0[i] = __shfl_sync(FULL, rv,      h00 + i + 1);
        f1[i] = __shfl_sync(FULL, rv, 10 + h01 + i + 1);
        f2[i] = __shfl_sync(FULL, rv, 20 + h02 + i + 1);
    }

    // ---- batch ALL gathers into distinct registers (max MLP) ----
    const float4 z = make_float4(0.f, 0.f, 0.f, 0.f);
    float4 a0 = ld4g(emb_type + t0 * EMB + lane4);
    float4 a1 = ld4g(emb_type + t1 * EMB + lane4);
    float4 a2 = ld4g(emb_type + t2 * EMB + lane4);

    float4 e0[4], e1[4], e2[4];
    #pragma unroll
    for (int i = 0; i < 4; i++) {
        const float* p0 = emb_feats + ((long long)(h00 + i) * CARD + f0[i]) * EMB + lane4;
        e0[i] = (i < nh0) ? ld4g(p0) : z;
    }
    #pragma unroll
    for (int i = 0; i < 4; i++) {
        const float* p1 = emb_feats + ((long long)(h01 + i) * CARD + f1[i]) * EMB + lane4;
        e1[i] = (i < nh1) ? ld4g(p1) : z;
    }
    #pragma unroll
    for (int i = 0; i < 4; i++) {
        const float* p2 = emb_feats + ((long long)(h02 + i) * CARD + f2[i]) * EMB + lane4;
        e2[i] = (i < nh2) ? ld4g(p2) : z;
    }

    // ---- accumulate (unconditional) ----
    #pragma unroll
    for (int i = 0; i < 4; i++) {
        a0.x += e0[i].x; a0.y += e0[i].y; a0.z += e0[i].z; a0.w += e0[i].w;
        a1.x += e1[i].x; a1.y += e1[i].y; a1.z += e1[i].z; a1.w += e1[i].w;
        a2.x += e2[i].x; a2.y += e2[i].y; a2.z += e2[i].z; a2.w += e2[i].w;
    }

    float4 ow = ld4(out_w + lane4);

    float pp = fmaxf(a0.x + a1.x, 0.f) * ow.x
             + fmaxf(a0.y + a1.y, 0.f) * ow.y
             + fmaxf(a0.z + a1.z, 0.f) * ow.z
             + fmaxf(a0.w + a1.w, 0.f) * ow.w;
    float np = fmaxf(a0.x + a2.x, 0.f) * ow.x
             + fmaxf(a0.y + a2.y, 0.f) * ow.y
             + fmaxf(a0.z + a2.z, 0.f) * ow.z
             + fmaxf(a0.w + a2.w, 0.f) * ow.w;

    pp += m;
    np += m;

    #pragma unroll
    for (int o = 16; o > 0; o >>= 1) {
        pp += __shfl_xor_sync(FULL, pp, o);
        np += __shfl_xor_sync(FULL, np, o);
    }

    if (lane == 0) {
        float c = g_c;
        out[e]     = pp + c;   // pos
        out[E + e] = np + c;   // neg
    }
}

extern "C" void kernel_launch(void* const* d_in, const int* in_sizes, int n_in,
                              void* d_out, int out_size) {
    const int*   x        = (const int*)  d_in[0];
    const int*   src      = (const int*)  d_in[1];
    const int*   dst      = (const int*)  d_in[2];
    const int*   neg_dst  = (const int*)  d_in[3];
    const float* msg      = (const float*)d_in[4];
    const float* emb_type = (const float*)d_in[5];
    const float* emb_feats= (const float*)d_in[6];
    const float* edge_w   = (const float*)d_in[7];
    const float* edge_b   = (const float*)d_in[8];
    const float* out_w    = (const float*)d_in[9];
    const float* out_b    = (const float*)d_in[10];
    float* out = (float*)d_out;

    int E = in_sizes[1];

    precompute_v_kernel<<<1, 32>>>(edge_w, edge_b, out_w, out_b);

    int threads = 256;
    int warps_per_block = threads / 32;
    int blocks = (E + warps_per_block - 1) / warps_per_block;
    edge_pred_kernel<<<blocks, threads>>>(x, src, dst, neg_dst, msg,
                                          emb_type, emb_feats, out_w, out, E);
}

// round 6
// speedup vs baseline: 4.0743x; 1.0407x over previous
#include <cuda_runtime.h>

// Problem constants (match reference)
#define N_FEAT_COLS 9
#define CARD 50000
#define EMB 128
#define EDGE_DIM 27

// Precomputed: v[j] = sum_k out_w[k] * edge_w[k][j]   (27 values)
//              g_c  = out_b[0] + sum_k out_w[k] * edge_b[k]
__device__ float g_v[EDGE_DIM];
__device__ float g_c;

__global__ void precompute_v_kernel(const float* __restrict__ edge_w,
                                    const float* __restrict__ edge_b,
                                    const float* __restrict__ out_w,
                                    const float* __restrict__ out_b) {
    int j = threadIdx.x;
    if (j < EDGE_DIM) {
        float s = 0.f;
        #pragma unroll 8
        for (int k = 0; k < EMB; k++) s += out_w[k] * edge_w[k * EDGE_DIM + j];
        g_v[j] = s;
    }
    if (j == EDGE_DIM) {
        float s = out_b[0];
        #pragma unroll 8
        for (int k = 0; k < EMB; k++) s += out_w[k] * edge_b[k];
        g_c = s;
    }
}

// Pinned gather: tables h=0..3 (102 MB) stay resident in L2 across the run.
__device__ __forceinline__ float4 ld4_hot(const float* __restrict__ p) {
    float4 v;
    asm("{\n\t"
        ".reg .b64 pol;\n\t"
        "createpolicy.fractional.L2::evict_last.b64 pol, 1.0;\n\t"
        "ld.global.nc.L2::cache_hint.v4.f32 {%0,%1,%2,%3}, [%4], pol;\n\t"
        "}"
        : "=f"(v.x), "=f"(v.y), "=f"(v.z), "=f"(v.w) : "l"(p));
    return v;
}
__device__ __forceinline__ float4 ld4g(const float* __restrict__ p) {
    return __ldg(reinterpret_cast<const float4*>(p));
}
__device__ __forceinline__ float4 ld4(const float* __restrict__ p) {
    return *reinterpret_cast<const float4*>(p);
}

// Encode one node's 128-dim embedding; each lane holds 4 contiguous floats.
// rv: this lane's x-row value bundle; base = which*10 offset within rv shuffles.
// Type-0 nodes hit tables 0..3 => pinned path (warp-uniform branch).
__device__ __forceinline__ float4 encode_node(int rv, int base, int lane4,
                                              const float* __restrict__ emb_type,
                                              const float* __restrict__ emb_feats) {
    const unsigned FULL = 0xffffffffu;
    int t = __shfl_sync(FULL, rv, base);  // type (uniform across warp)
    float4 acc = ld4(emb_type + t * EMB + lane4);   // tiny table, resident
    // TYPE_PER_COL = (0,0,0,0,1,2,2,2,2):
    //   t==0 -> cols 0..3, t==1 -> col 4, t==2 -> cols 5..8
    int h0 = (t == 0) ? 0 : (t == 1) ? 4 : 5;
    int nh = (t == 1) ? 1 : 4;
    bool pinned = (t == 0);
    #pragma unroll 4
    for (int i = 0; i < 4; i++) {
        if (i < nh) {
            int h = h0 + i;
            int f = __shfl_sync(FULL, rv, base + h + 1);
            const float* p = emb_feats + ((long long)h * CARD + f) * EMB + lane4;
            float4 e = pinned ? ld4_hot(p) : ld4g(p);
            acc.x += e.x; acc.y += e.y; acc.z += e.z; acc.w += e.w;
        }
    }
    return acc;
}

__global__ __launch_bounds__(256)
void edge_pred_kernel(const int* __restrict__ x,
                      const int* __restrict__ src,
                      const int* __restrict__ dst,
                      const int* __restrict__ neg_dst,
                      const float* __restrict__ msg,
                      const float* __restrict__ emb_type,
                      const float* __restrict__ emb_feats,
                      const float* __restrict__ out_w,
                      float* __restrict__ out,
                      int E) {
    const unsigned FULL = 0xffffffffu;
    int warp = (blockIdx.x * blockDim.x + threadIdx.x) >> 5;
    int lane = threadIdx.x & 31;
    if (warp >= E) return;
    int e = warp;

    // Index arrays: single-use, fully coalesced -> streaming.
    int s  = __ldcs(src + e);
    int d  = __ldcs(dst + e);
    int nd = __ldcs(neg_dst + e);

    // Lanes 0..29 cooperatively load the three 10-int x rows in one LDG.
    // x lines carry ~2.4 refs each across the run -> keep cached (NOT .cs).
    int which = lane / 10;          // 0:src 1:dst 2:neg
    int off   = lane - which * 10;
    int nid   = (which == 0) ? s : (which == 1) ? d : nd;
    int rv = 0;
    if (lane < 30) rv = __ldg(x + (long long)nid * 10 + off);

    // msg dot with precomputed v (single-use -> streaming; issue early)
    float m = 0.f;
    if (lane < EDGE_DIM)
        m = __ldcs(msg + (long long)e * EDGE_DIM + lane) * g_v[lane];

    int lane4 = lane * 4;
    float4 hs = encode_node(rv, 0,  lane4, emb_type, emb_feats);
    float4 hd = encode_node(rv, 10, lane4, emb_type, emb_feats);
    float4 hn = encode_node(rv, 20, lane4, emb_type, emb_feats);

    float4 ow = ld4(out_w + lane4);

    float pp = fmaxf(hs.x + hd.x, 0.f) * ow.x
             + fmaxf(hs.y + hd.y, 0.f) * ow.y
             + fmaxf(hs.z + hd.z, 0.f) * ow.z
             + fmaxf(hs.w + hd.w, 0.f) * ow.w;
    float np = fmaxf(hs.x + hn.x, 0.f) * ow.x
             + fmaxf(hs.y + hn.y, 0.f) * ow.y
             + fmaxf(hs.z + hn.z, 0.f) * ow.z
             + fmaxf(hs.w + hn.w, 0.f) * ow.w;

    pp += m;
    np += m;

    #pragma unroll
    for (int o = 16; o > 0; o >>= 1) {
        pp += __shfl_xor_sync(FULL, pp, o);
        np += __shfl_xor_sync(FULL, np, o);
    }

    if (lane == 0) {
        float c = g_c;
        out[e]     = pp + c;   // pos
        out[E + e] = np + c;   // neg
    }
}

extern "C" void kernel_launch(void* const* d_in, const int* in_sizes, int n_in,
                              void* d_out, int out_size) {
    const int*   x        = (const int*)  d_in[0];
    const int*   src      = (const int*)  d_in[1];
    const int*   dst      = (const int*)  d_in[2];
    const int*   neg_dst  = (const int*)  d_in[3];
    const float* msg      = (const float*)d_in[4];
    const float* emb_type = (const float*)d_in[5];
    const float* emb_feats= (const float*)d_in[6];
    const float* edge_w   = (const float*)d_in[7];
    const float* edge_b   = (const float*)d_in[8];
    const float* out_w    = (const float*)d_in[9];
    const float* out_b    = (const float*)d_in[10];
    float* out = (float*)d_out;

    int E = in_sizes[1];

    precompute_v_kernel<<<1, 32>>>(edge_w, edge_b, out_w, out_b);

    int threads = 256;
    int warps_per_block = threads / 32;
    int blocks = (E + warps_per_block - 1) / warps_per_block;
    edge_pred_kernel<<<blocks, threads>>>(x, src, dst, neg_dst, msg,
                                          emb_type, emb_feats, out_w, out, E);
}